// round 1
// baseline (speedup 1.0000x reference)
#include <cuda_runtime.h>

// InverseFrequencyLoss: fused single-pass over logits.
// inputs [B,C,H,W] f32, targets [B,H,W] i32 -> scalar f32.
// Pass 1 (fused): per-pixel logsumexp NLL, accumulated per-class (count, sum_nll).
// Pass 2 (tiny):  result = sum_c inv_freq[c]*nll_sum[c] / sum_c count[c]*inv_freq[c].

#define NCLS 19
#define BB   8
#define HH   512
#define WW   1024
#define HWSZ (HH * WW)            // 524288 = 2^19
#define NPIX (BB * HWSZ)          // 4,194,304

__device__ unsigned int g_count[NCLS];
__device__ double       g_nll[NCLS];

__global__ void init_kernel() {
    int i = threadIdx.x;
    if (i < NCLS) { g_count[i] = 0u; g_nll[i] = 0.0; }
}

__global__ __launch_bounds__(256) void main_kernel(const float* __restrict__ in,
                                                   const int* __restrict__ tgt) {
    __shared__ unsigned int s_count[NCLS];
    __shared__ float        s_nll[NCLS];

    int tid = threadIdx.x;
    if (tid < NCLS) { s_count[tid] = 0u; s_nll[tid] = 0.0f; }
    __syncthreads();

    int stride = gridDim.x * blockDim.x;
    for (int n = blockIdx.x * blockDim.x + tid; n < NPIX; n += stride) {
        int b  = n >> 19;          // n / HWSZ
        int hw = n & (HWSZ - 1);   // n % HWSZ
        const float* p = in + (size_t)b * NCLS * HWSZ + hw;
        int t = tgt[n];

        // Load all 19 class logits (coalesced per plane), track max and x_target.
        float x[NCLS];
        float mx = -1e30f;
        #pragma unroll
        for (int c = 0; c < NCLS; c++) {
            x[c] = p[(size_t)c * HWSZ];
            mx = fmaxf(mx, x[c]);
        }
        float xt = x[0];
        #pragma unroll
        for (int c = 1; c < NCLS; c++) {
            xt = (t == c) ? x[c] : xt;
        }

        float S = 0.0f;
        #pragma unroll
        for (int c = 0; c < NCLS; c++) {
            S += __expf(x[c] - mx);
        }
        float nll = mx + __logf(S) - xt;   // = logsumexp - x_t >= 0

        atomicAdd(&s_nll[t], nll);
        atomicAdd(&s_count[t], 1u);
    }
    __syncthreads();

    if (tid < NCLS) {
        unsigned int c = s_count[tid];
        if (c) atomicAdd(&g_count[tid], c);
        float v = s_nll[tid];
        if (v != 0.0f) atomicAdd(&g_nll[tid], (double)v);
    }
}

__global__ void finalize_kernel(float* __restrict__ out) {
    double num = 0.0, den = 0.0;
    #pragma unroll
    for (int c = 0; c < NCLS; c++) {
        unsigned int cnt = g_count[c];
        if (cnt > 0) {
            double inv = 1.0 / (double)cnt;
            num += inv * g_nll[c];
            den += inv * (double)cnt;   // == 1.0 per present class
        }
    }
    out[0] = (float)(num / den);
}

extern "C" void kernel_launch(void* const* d_in, const int* in_sizes, int n_in,
                              void* d_out, int out_size) {
    const float* in  = (const float*)d_in[0];
    const int*   tgt = (const int*)d_in[1];
    float*       out = (float*)d_out;

    init_kernel<<<1, 32>>>();
    main_kernel<<<4096, 256>>>(in, tgt);
    finalize_kernel<<<1, 1>>>(out);
}